// round 16
// baseline (speedup 1.0000x reference)
#include <cuda_runtime.h>
#include <cuda_fp16.h>
#include <cstdint>
#include <cstddef>

#define TOK 64
#define NF 8192
#define MF 8192
#define SPLITS 4
#define KSPLIT 2048        /* NF / SPLITS */
#define KTILE 128
#define CHUNKS 16          /* KSPLIT / KTILE */
#define MTILE 128

// ---- scratch (allocation-free rule: device globals) ----
__device__ __half g_xh[TOK * NF];                    // 1 MB  FHT'd activations fp16
__device__ __half g_yph[(size_t)SPLITS * TOK * MF];  // 4 MB  split-K partials fp16

// ---- k_gemm dynamic smem layout (XOR-swizzled tiles, dup codebooks) ----
#define OFF_CB1  0                       /* cb1 copy0 @0, copy1 @4096          */
#define OFF_CB2  8192                    /* cb2 copy0 @8192, copy1 @12288      */
#define OFF_W0   16384                   /* W buf: 128 rows x 256B = 32 KB     */
#define OFF_W1   (OFF_W0 + 32768)
#define OFF_X0   (OFF_W1 + 32768)        /* X buf: 64 rows x 256B = 16 KB      */
#define OFF_X1   (OFF_X0 + 16384)
#define SMEM_SZ  (OFF_X1 + 16384)        /* 114688 B = 112 KB -> 2 CTAs/SM     */
#define OBPAD 132                        /* epilogue fp32 row stride           */

// swizzled byte offset of (row, 16B-seg) within a tile (256B rows, 16 segs)
#define SWZ(row, seg) (((row) << 8) + ((((seg) ^ ((row) & 7))) << 4))

// named barriers: ready[b] = 1+b, consumed[b] = 3+b
#define BAR_READY(b)    (1 + (b))
#define BAR_CONSUMED(b) (3 + (b))

__device__ __forceinline__ uint32_t smem_u32(const void* p) {
    return (uint32_t)__cvta_generic_to_shared(p);
}
__device__ __forceinline__ void bar_sync(int id) {
    asm volatile("bar.sync %0, 256;" :: "r"(id) : "memory");
}
__device__ __forceinline__ void bar_arrive(int id) {
    asm volatile("bar.arrive %0, 256;" :: "r"(id) : "memory");
}
__device__ __forceinline__ void cp_async16(uint32_t dst, const void* src) {
    asm volatile("cp.async.cg.shared.global [%0], [%1], 16;" :: "r"(dst), "l"(src) : "memory");
}

// ---------------------------------------------------------------------------
// register FHT helpers
// ---------------------------------------------------------------------------
template <int N>
__device__ __forceinline__ void fht_regs(float* v) {
    #pragma unroll
    for (int h = 1; h < N; h <<= 1)
        #pragma unroll
        for (int i = 0; i < N; ++i)
            if ((i & h) == 0) { float a = v[i], b = v[i + h]; v[i] = a + b; v[i + h] = a - b; }
}
__device__ __forceinline__ int pad(int i) { return i + (i >> 5); }

// ---------------------------------------------------------------------------
// FHT-2048 with 512 threads, 4 elems/thread (2 barriers):
//  - h = 1,2 in regs; h = 4..64 via shfl.bfly; two smem radix-4 rounds
//  Result: u[j] = FHT output at position (t&127) + 128*(t>>7) + 512*j.
// ---------------------------------------------------------------------------
__device__ __forceinline__ void fht2048_512(float* s, float* v, float* u,
                                            int t, int lane) {
    fht_regs<4>(v);                                  // h = 1,2
    #pragma unroll
    for (int d = 1; d < 32; d <<= 1) {               // h = 4,8,16,32,64
        #pragma unroll
        for (int j = 0; j < 4; ++j) {
            float o = __shfl_xor_sync(0xffffffffu, v[j], d);
            v[j] = (lane & d) ? (o - v[j]) : (v[j] + o);
        }
    }
    #pragma unroll
    for (int j = 0; j < 4; ++j) s[pad(t * 4 + j)] = v[j];
    __syncthreads();
    const int l = t & 127, g = t >> 7;
    #pragma unroll
    for (int j = 0; j < 4; ++j) u[j] = s[pad(l + 512 * g + 128 * j)];
    fht_regs<4>(u);                                  // h = 128,256
    #pragma unroll
    for (int j = 0; j < 4; ++j) s[pad(l + 512 * g + 128 * j)] = u[j];
    __syncthreads();
    #pragma unroll
    for (int j = 0; j < 4; ++j) u[j] = s[pad(l + 128 * g + 512 * j)];
    fht_regs<4>(u);                                  // h = 512,1024
}

// ---------------------------------------------------------------------------
// Kernel 1: fused H4-across-blocks + FHT-2048 of x*SV -> g_xh (fp16)
//   grid = (TOK, 4), 512 threads
// ---------------------------------------------------------------------------
__global__ void __launch_bounds__(512) k_fht_in(const float* __restrict__ x,
                                                const float* __restrict__ SV) {
    __shared__ float s[2048 + 64];
    const int row = blockIdx.x, q = blockIdx.y, t = threadIdx.x, lane = t & 31;
    float v[4], u[4];
    #pragma unroll
    for (int e = 0; e < 4; ++e) v[e] = 0.f;
    #pragma unroll
    for (int j = 0; j < 4; ++j) {
        const float sgn = (__popc(q & j) & 1) ? -1.f : 1.f;
        float4 a = *(const float4*)(x + (size_t)row * NF + j * 2048 + t * 4);
        float4 b = *(const float4*)(SV + j * 2048 + t * 4);
        v[0] += sgn * a.x * b.x; v[1] += sgn * a.y * b.y;
        v[2] += sgn * a.z * b.z; v[3] += sgn * a.w * b.w;
    }
    fht2048_512(s, v, u, t, lane);
    const float sc = 0.011048543456039806f;  // 1/sqrt(8192)
    const int l = t & 127, g = t >> 7;
    __half* dst = g_xh + (size_t)row * NF + q * 2048 + l + 128 * g;
    #pragma unroll
    for (int j = 0; j < 4; ++j) dst[512 * j] = __float2half(u[j] * sc);
}

// ---------------------------------------------------------------------------
// Kernel 2: warp-specialized dequant + HMMA GEMM (swizzled tiles)
//   grid = (MF/MTILE, SPLITS) = (64, 4), 256 threads
//   warps 0-3: consumers (fp16-accum MMA + per-kk fp32 flush, 32m x 64n)
//   warps 4-7: producers (decode W + cp.async X)
// ---------------------------------------------------------------------------
__global__ void __launch_bounds__(256, 2) k_gemm(const int*   __restrict__ Qidxs,
                                                 const int*   __restrict__ Qidxs2,
                                                 const float* __restrict__ cb1g,
                                                 const float* __restrict__ cb2g,
                                                 const float* __restrict__ irs_p) {
    extern __shared__ char smem[];
    const int t = threadIdx.x, w = t >> 5, lane = t & 31;
    const int m0 = blockIdx.x * MTILE, split = blockIdx.y;
    const uint32_t sb = smem_u32(smem);

    // ---- fp16 codebooks, 2 copies each (cb2 pre-scaled by inv_resid_scale) ----
    {
        const float irs = irs_p[0];
        const float4* p1 = (const float4*)(cb1g + t * 8);
        const float4* p2 = (const float4*)(cb2g + t * 8);
        float4 a0 = p1[0], a1 = p1[1], b0 = p2[0], b1 = p2[1];
        union { uint4 u; __half2 h[4]; } pk;
        pk.h[0] = __floats2half2_rn(a0.x, a0.y); pk.h[1] = __floats2half2_rn(a0.z, a0.w);
        pk.h[2] = __floats2half2_rn(a1.x, a1.y); pk.h[3] = __floats2half2_rn(a1.z, a1.w);
        ((uint4*)(smem + OFF_CB1))[t] = pk.u;
        ((uint4*)(smem + OFF_CB1 + 4096))[t] = pk.u;
        pk.h[0] = __floats2half2_rn(b0.x * irs, b0.y * irs);
        pk.h[1] = __floats2half2_rn(b0.z * irs, b0.w * irs);
        pk.h[2] = __floats2half2_rn(b1.x * irs, b1.y * irs);
        pk.h[3] = __floats2half2_rn(b1.z * irs, b1.w * irs);
        ((uint4*)(smem + OFF_CB2))[t] = pk.u;
        ((uint4*)(smem + OFF_CB2 + 4096))[t] = pk.u;
    }
    __syncthreads();   // codebooks visible to producer gathers

    float acc[2][8][4];   // consumer accumulators (32m x 64n)

    if (w < 4) {
        // ================= CONSUMER =================
        #pragma unroll
        for (int mi = 0; mi < 2; ++mi)
            #pragma unroll
            for (int nt = 0; nt < 8; ++nt)
                #pragma unroll
                for (int e = 0; e < 4; ++e) acc[mi][nt][e] = 0.f;

        for (int c = 0; c < CHUNKS; ++c) {
            const int b = c & 1;
            bar_sync(BAR_READY(b));
            const char* ws = smem + (b ? OFF_W1 : OFF_W0);
            const char* xs = smem + (b ? OFF_X1 : OFF_X0);
            #pragma unroll
            for (int kk = 0; kk < 8; ++kk) {
                uint32_t A[2][4], B[8][2];
                #pragma unroll
                for (int mi = 0; mi < 2; ++mi) {
                    int row = w * 32 + mi * 16 + (lane & 15);
                    int seg = kk * 2 + (lane >> 4);
                    uint32_t ad = smem_u32(ws + SWZ(row, seg));
                    asm volatile("ldmatrix.sync.aligned.m8n8.x4.shared.b16 {%0,%1,%2,%3}, [%4];"
                                 : "=r"(A[mi][0]), "=r"(A[mi][1]), "=r"(A[mi][2]), "=r"(A[mi][3])
                                 : "r"(ad));
                }
                #pragma unroll
                for (int g = 0; g < 4; ++g) {   // 2 token-tiles per x4
                    int row = g * 16 + (lane & 15);
                    int seg = kk * 2 + (lane >> 4);
                    uint32_t bd = smem_u32(xs + SWZ(row, seg));
                    uint32_t r0, r1, r2, r3;
                    asm volatile("ldmatrix.sync.aligned.m8n8.x4.shared.b16 {%0,%1,%2,%3}, [%4];"
                                 : "=r"(r0), "=r"(r1), "=r"(r2), "=r"(r3) : "r"(bd));
                    B[2 * g][0] = r0;     B[2 * g][1] = r2;
                    B[2 * g + 1][0] = r1; B[2 * g + 1][1] = r3;
                }
                // fp16-accum MMA, transient D, immediate fp32 flush.
                // Each k16 dot rounds to fp16 once at small magnitude (~4),
                // then accumulates in fp32: adds ~1.4e-4 rel err in quadrature.
                #pragma unroll
                for (int mi = 0; mi < 2; ++mi)
                    #pragma unroll
                    for (int nt = 0; nt < 8; ++nt) {
                        uint32_t d0 = 0u, d1 = 0u;
                        asm volatile("mma.sync.aligned.m16n8k16.row.col.f16.f16.f16.f16 "
                                     "{%0,%1}, {%2,%3,%4,%5}, {%6,%7}, {%0,%1};"
                                     : "+r"(d0), "+r"(d1)
                                     : "r"(A[mi][0]), "r"(A[mi][1]), "r"(A[mi][2]), "r"(A[mi][3]),
                                       "r"(B[nt][0]), "r"(B[nt][1]));
                        float2 f0 = __half22float2(*reinterpret_cast<__half2*>(&d0));
                        float2 f1 = __half22float2(*reinterpret_cast<__half2*>(&d1));
                        acc[mi][nt][0] += f0.x; acc[mi][nt][1] += f0.y;
                        acc[mi][nt][2] += f1.x; acc[mi][nt][3] += f1.y;
                    }
            }
            bar_arrive(BAR_CONSUMED(b));
        }
    } else {
        // ================= PRODUCER =================
        const int pt = t - 128;                  // 0..127 = W row within tile
        const uint4* cb1 = (const uint4*)(smem + OFF_CB1 + (lane & 1) * 4096);
        const uint4* cb2 = (const uint4*)(smem + OFF_CB2 + (lane & 1) * 4096);
        const int* q1base = Qidxs  + (size_t)(m0 + pt) * (NF / 8) + split * (KSPLIT / 8);
        const int* q2base = Qidxs2 + (size_t)(m0 + pt) * (NF / 8) + split * (KSPLIT / 8);

        int4 c1[4], c2[4], n1[4], n2[4];
        #pragma unroll
        for (int i = 0; i < 4; ++i) {            // prime chunk 0 indices
            c1[i] = *(const int4*)(q1base + i * 4);
            c2[i] = *(const int4*)(q2base + i * 4);
        }

        for (int c = 0; c < CHUNKS; ++c) {
            const int b = c & 1;
            if (c >= 2) bar_sync(BAR_CONSUMED(b));

            // stage X tile via cp.async into swizzled layout
            const int k0 = split * KSPLIT + c * KTILE;
            const uint32_t xb = sb + (b ? OFF_X1 : OFF_X0);
            #pragma unroll
            for (int i = 0; i < 8; ++i) {
                int idx = pt + 128 * i, tok = idx >> 4, seg = idx & 15;
                cp_async16(xb + SWZ(tok, seg),
                           g_xh + (size_t)tok * NF + k0 + seg * 8);
            }
            asm volatile("cp.async.commit_group;" ::: "memory");

            // prefetch next chunk's indices (hidden under decode below)
            if (c + 1 < CHUNKS) {
                #pragma unroll
                for (int i = 0; i < 4; ++i) {
                    n1[i] = *(const int4*)(q1base + (c + 1) * 16 + i * 4);
                    n2[i] = *(const int4*)(q2base + (c + 1) * 16 + i * 4);
                }
            }

            // decode this chunk's 16 groups for row pt into swizzled W
            {
                int q1[16] = {c1[0].x, c1[0].y, c1[0].z, c1[0].w,
                              c1[1].x, c1[1].y, c1[1].z, c1[1].w,
                              c1[2].x, c1[2].y, c1[2].z, c1[2].w,
                              c1[3].x, c1[3].y, c1[3].z, c1[3].w};
                int q2[16] = {c2[0].x, c2[0].y, c2[0].z, c2[0].w,
                              c2[1].x, c2[1].y, c2[1].z, c2[1].w,
                              c2[2].x, c2[2].y, c2[2].z, c2[2].w,
                              c2[3].x, c2[3].y, c2[3].z, c2[3].w};
                char* wb = smem + (b ? OFF_W1 : OFF_W0);
                const uint32_t rbase = pt << 8;
                const uint32_t rx = (pt & 7) << 4;
                #pragma unroll
                for (int j = 0; j < 16; ++j) {
                    uint4 v1 = cb1[q1[j]], v2 = cb2[q2[j]];
                    __half2* h1 = (__half2*)&v1;
                    const __half2* h2 = (const __half2*)&v2;
                    h1[0] = __hadd2(h1[0], h2[0]); h1[1] = __hadd2(h1[1], h2[1]);
                    h1[2] = __hadd2(h1[2], h2[2]); h1[3] = __hadd2(h1[3], h2[3]);
                    *(uint4*)(wb + (rbase + (((uint32_t)(j << 4)) ^ rx))) = v1;
                }
            }

            asm volatile("cp.async.wait_group 0;" ::: "memory");
            bar_arrive(BAR_READY(b));

            #pragma unroll
            for (int i = 0; i < 4; ++i) { c1[i] = n1[i]; c2[i] = n2[i]; }
        }
    }

    // ---- epilogue: consumer regs -> smem transpose [tok][m] -> fp16 partials ----
    float* ob = (float*)(smem + OFF_W0);    // 64 * OBPAD * 4 = 33792 B (W bufs dead)
    __syncthreads();
    if (w < 4) {
        #pragma unroll
        for (int mi = 0; mi < 2; ++mi)
            #pragma unroll
            for (int nt = 0; nt < 8; ++nt) {
                int m = w * 32 + mi * 16 + (lane >> 2);
                int n = nt * 8 + (lane & 3) * 2;
                ob[n * OBPAD + m]           = acc[mi][nt][0];
                ob[(n + 1) * OBPAD + m]     = acc[mi][nt][1];
                ob[n * OBPAD + m + 8]       = acc[mi][nt][2];
                ob[(n + 1) * OBPAD + m + 8] = acc[mi][nt][3];
            }
    }
    __syncthreads();
    __half* dst = g_yph + (size_t)split * TOK * MF;
    #pragma unroll
    for (int i = 0; i < 4; ++i) {
        int idx = t + 256 * i;              // 0..1023: tok = idx>>4, 8-val seg
        int tok = idx >> 4, seg = idx & 15;
        const float* src = ob + tok * OBPAD + seg * 8;
        union { uint4 u; __half2 h[4]; } pk;
        #pragma unroll
        for (int e = 0; e < 4; ++e)
            pk.h[e] = __floats2half2_rn(src[2 * e], src[2 * e + 1]);
        *(uint4*)(dst + (size_t)tok * MF + m0 + seg * 8) = pk.u;
    }
}

// ---------------------------------------------------------------------------
// Kernel 3: fused split-reduce + H4-across-blocks + FHT-2048 + scale/SU -> out
//   grid = (TOK, 4), 512 threads
// ---------------------------------------------------------------------------
__global__ void __launch_bounds__(512) k_fht_out(float* __restrict__ out,
                                                 const float* __restrict__ SU,
                                                 const float* __restrict__ wsc_p) {
    __shared__ float s[2048 + 64];
    const int row = blockIdx.x, q = blockIdx.y, t = threadIdx.x, lane = t & 31;
    float v[4], u[4];
    #pragma unroll
    for (int e = 0; e < 4; ++e) v[e] = 0.f;
    #pragma unroll
    for (int j = 0; j < 4; ++j) {
        const float sgn = (__popc(q & j) & 1) ? -1.f : 1.f;
        #pragma unroll
        for (int sp = 0; sp < SPLITS; ++sp) {
            union { uint2 u2; __half2 h[2]; } pk;
            pk.u2 = *(const uint2*)(g_yph + ((size_t)sp * TOK + row) * MF + j * 2048 + t * 4);
            float2 f0 = __half22float2(pk.h[0]);
            float2 f1 = __half22float2(pk.h[1]);
            v[0] += sgn * f0.x; v[1] += sgn * f0.y;
            v[2] += sgn * f1.x; v[3] += sgn * f1.y;
        }
    }
    fht2048_512(s, v, u, t, lane);
    const float sc = wsc_p[0] * 0.011048543456039806f;  // Wscale / sqrt(8192)
    const int l = t & 127, g = t >> 7;
    const int col = q * 2048 + l + 128 * g;
    float* op = out + (size_t)row * MF + col;
    const float* sup = SU + col;
    #pragma unroll
    for (int j = 0; j < 4; ++j)
        op[512 * j] = u[j] * sc * sup[512 * j];
}

// ---------------------------------------------------------------------------
extern "C" void kernel_launch(void* const* d_in, const int* in_sizes, int n_in,
                              void* d_out, int out_size) {
    const float* x      = (const float*)d_in[0];
    const int*   Qidxs  = (const int*)  d_in[1];
    const int*   Qidxs2 = (const int*)  d_in[2];
    const float* cb1    = (const float*)d_in[3];
    const float* cb2    = (const float*)d_in[4];
    const float* SU     = (const float*)d_in[5];
    const float* SV     = (const float*)d_in[6];
    const float* Wsc    = (const float*)d_in[7];
    const float* irs    = (const float*)d_in[8];
    float* out = (float*)d_out;

    cudaFuncSetAttribute(k_gemm, cudaFuncAttributeMaxDynamicSharedMemorySize, SMEM_SZ);

    k_fht_in<<<dim3(TOK, 4), 512>>>(x, SV);
    k_gemm<<<dim3(MF / MTILE, SPLITS), 256, SMEM_SZ>>>(Qidxs, Qidxs2, cb1, cb2, irs);
    k_fht_out<<<dim3(TOK, 4), 512>>>(out, SU, Wsc);
}

// round 17
// speedup vs baseline: 1.0779x; 1.0779x over previous
#include <cuda_runtime.h>
#include <cuda_fp16.h>
#include <cstdint>
#include <cstddef>

#define TOK 64
#define NF 8192
#define MF 8192
#define SPLITS 4
#define KSPLIT 2048        /* NF / SPLITS */
#define KTILE 128
#define CHUNKS 16          /* KSPLIT / KTILE */
#define MTILE 128

// ---- scratch (allocation-free rule: device globals) ----
__device__ __half g_xh[TOK * NF];                    // 1 MB  FHT'd activations fp16
__device__ __half g_yph[(size_t)SPLITS * TOK * MF];  // 4 MB  split-K partials fp16

// ---- k_gemm dynamic smem layout (XOR-swizzled tiles, dup codebooks) ----
#define OFF_CB1  0                       /* cb1 copy0 @0, copy1 @4096          */
#define OFF_CB2  8192                    /* cb2 copy0 @8192, copy1 @12288      */
#define OFF_W0   16384                   /* W buf: 128 rows x 256B = 32 KB     */
#define OFF_W1   (OFF_W0 + 32768)
#define OFF_X0   (OFF_W1 + 32768)        /* X buf: 64 rows x 256B = 16 KB      */
#define OFF_X1   (OFF_X0 + 16384)
#define SMEM_SZ  (OFF_X1 + 16384)        /* 114688 B = 112 KB -> 2 CTAs/SM     */
#define OBPAD 132                        /* epilogue fp32 row stride           */

// swizzled byte offset of (row, 16B-seg) within a tile (256B rows, 16 segs)
#define SWZ(row, seg) (((row) << 8) + ((((seg) ^ ((row) & 7))) << 4))

// named barriers: ready[b] = 1+b, consumed[b] = 3+b
#define BAR_READY(b)    (1 + (b))
#define BAR_CONSUMED(b) (3 + (b))

__device__ __forceinline__ uint32_t smem_u32(const void* p) {
    return (uint32_t)__cvta_generic_to_shared(p);
}
__device__ __forceinline__ void bar_sync(int id) {
    asm volatile("bar.sync %0, 256;" :: "r"(id) : "memory");
}
__device__ __forceinline__ void bar_arrive(int id) {
    asm volatile("bar.arrive %0, 256;" :: "r"(id) : "memory");
}
__device__ __forceinline__ void cp_async16(uint32_t dst, const void* src) {
    asm volatile("cp.async.cg.shared.global [%0], [%1], 16;" :: "r"(dst), "l"(src) : "memory");
}

// ---------------------------------------------------------------------------
// register FHT helpers
// ---------------------------------------------------------------------------
template <int N>
__device__ __forceinline__ void fht_regs(float* v) {
    #pragma unroll
    for (int h = 1; h < N; h <<= 1)
        #pragma unroll
        for (int i = 0; i < N; ++i)
            if ((i & h) == 0) { float a = v[i], b = v[i + h]; v[i] = a + b; v[i + h] = a - b; }
}
__device__ __forceinline__ int pad(int i) { return i + (i >> 5); }

// ---------------------------------------------------------------------------
// FHT-2048 with 512 threads, 4 elems/thread (2 barriers):
//  - h = 1,2 in regs; h = 4..64 via shfl.bfly; two smem radix-4 rounds
//  Result: u[j] = FHT output at position (t&127) + 128*(t>>7) + 512*j.
// ---------------------------------------------------------------------------
__device__ __forceinline__ void fht2048_512(float* s, float* v, float* u,
                                            int t, int lane) {
    fht_regs<4>(v);                                  // h = 1,2
    #pragma unroll
    for (int d = 1; d < 32; d <<= 1) {               // h = 4,8,16,32,64
        #pragma unroll
        for (int j = 0; j < 4; ++j) {
            float o = __shfl_xor_sync(0xffffffffu, v[j], d);
            v[j] = (lane & d) ? (o - v[j]) : (v[j] + o);
        }
    }
    #pragma unroll
    for (int j = 0; j < 4; ++j) s[pad(t * 4 + j)] = v[j];
    __syncthreads();
    const int l = t & 127, g = t >> 7;
    #pragma unroll
    for (int j = 0; j < 4; ++j) u[j] = s[pad(l + 512 * g + 128 * j)];
    fht_regs<4>(u);                                  // h = 128,256
    #pragma unroll
    for (int j = 0; j < 4; ++j) s[pad(l + 512 * g + 128 * j)] = u[j];
    __syncthreads();
    #pragma unroll
    for (int j = 0; j < 4; ++j) u[j] = s[pad(l + 128 * g + 512 * j)];
    fht_regs<4>(u);                                  // h = 512,1024
}

// ---------------------------------------------------------------------------
// Kernel 1: fused H4-across-blocks + FHT-2048 of x*SV -> g_xh (fp16)
//   grid = (TOK, 4), 512 threads; all 8 global loads batched first (MLP).
// ---------------------------------------------------------------------------
__global__ void __launch_bounds__(512) k_fht_in(const float* __restrict__ x,
                                                const float* __restrict__ SV) {
    __shared__ float s[2048 + 64];
    const int row = blockIdx.x, q = blockIdx.y, t = threadIdx.x, lane = t & 31;
    float4 a[4], b[4];
    #pragma unroll
    for (int j = 0; j < 4; ++j) {
        a[j] = *(const float4*)(x + (size_t)row * NF + j * 2048 + t * 4);
        b[j] = *(const float4*)(SV + j * 2048 + t * 4);
    }
    float v[4], u[4];
    #pragma unroll
    for (int e = 0; e < 4; ++e) v[e] = 0.f;
    #pragma unroll
    for (int j = 0; j < 4; ++j) {
        const float sgn = (__popc(q & j) & 1) ? -1.f : 1.f;
        v[0] += sgn * a[j].x * b[j].x; v[1] += sgn * a[j].y * b[j].y;
        v[2] += sgn * a[j].z * b[j].z; v[3] += sgn * a[j].w * b[j].w;
    }
    fht2048_512(s, v, u, t, lane);
    const float sc = 0.011048543456039806f;  // 1/sqrt(8192)
    const int l = t & 127, g = t >> 7;
    __half* dst = g_xh + (size_t)row * NF + q * 2048 + l + 128 * g;
    #pragma unroll
    for (int j = 0; j < 4; ++j) dst[512 * j] = __float2half(u[j] * sc);
}

// ---------------------------------------------------------------------------
// Kernel 2: warp-specialized dequant + HMMA GEMM (swizzled tiles) — champion
//   grid = (MF/MTILE, SPLITS) = (64, 4), 256 threads
//   warps 0-3: consumers (fp32-accum MMA, 32m x 64n);  warps 4-7: producers
// ---------------------------------------------------------------------------
__global__ void __launch_bounds__(256, 2) k_gemm(const int*   __restrict__ Qidxs,
                                                 const int*   __restrict__ Qidxs2,
                                                 const float* __restrict__ cb1g,
                                                 const float* __restrict__ cb2g,
                                                 const float* __restrict__ irs_p) {
    extern __shared__ char smem[];
    const int t = threadIdx.x, w = t >> 5, lane = t & 31;
    const int m0 = blockIdx.x * MTILE, split = blockIdx.y;
    const uint32_t sb = smem_u32(smem);

    // ---- fp16 codebooks, 2 copies each (cb2 pre-scaled by inv_resid_scale) ----
    {
        const float irs = irs_p[0];
        const float4* p1 = (const float4*)(cb1g + t * 8);
        const float4* p2 = (const float4*)(cb2g + t * 8);
        float4 a0 = p1[0], a1 = p1[1], b0 = p2[0], b1 = p2[1];
        union { uint4 u; __half2 h[4]; } pk;
        pk.h[0] = __floats2half2_rn(a0.x, a0.y); pk.h[1] = __floats2half2_rn(a0.z, a0.w);
        pk.h[2] = __floats2half2_rn(a1.x, a1.y); pk.h[3] = __floats2half2_rn(a1.z, a1.w);
        ((uint4*)(smem + OFF_CB1))[t] = pk.u;
        ((uint4*)(smem + OFF_CB1 + 4096))[t] = pk.u;
        pk.h[0] = __floats2half2_rn(b0.x * irs, b0.y * irs);
        pk.h[1] = __floats2half2_rn(b0.z * irs, b0.w * irs);
        pk.h[2] = __floats2half2_rn(b1.x * irs, b1.y * irs);
        pk.h[3] = __floats2half2_rn(b1.z * irs, b1.w * irs);
        ((uint4*)(smem + OFF_CB2))[t] = pk.u;
        ((uint4*)(smem + OFF_CB2 + 4096))[t] = pk.u;
    }
    __syncthreads();   // codebooks visible to producer gathers

    float acc[2][8][4];   // consumer accumulators (32m x 64n)

    if (w < 4) {
        // ================= CONSUMER =================
        #pragma unroll
        for (int mi = 0; mi < 2; ++mi)
            #pragma unroll
            for (int nt = 0; nt < 8; ++nt)
                #pragma unroll
                for (int e = 0; e < 4; ++e) acc[mi][nt][e] = 0.f;

        for (int c = 0; c < CHUNKS; ++c) {
            const int b = c & 1;
            bar_sync(BAR_READY(b));
            const char* ws = smem + (b ? OFF_W1 : OFF_W0);
            const char* xs = smem + (b ? OFF_X1 : OFF_X0);
            #pragma unroll
            for (int kk = 0; kk < 8; ++kk) {
                uint32_t A[2][4], B[8][2];
                #pragma unroll
                for (int mi = 0; mi < 2; ++mi) {
                    int row = w * 32 + mi * 16 + (lane & 15);
                    int seg = kk * 2 + (lane >> 4);
                    uint32_t ad = smem_u32(ws + SWZ(row, seg));
                    asm volatile("ldmatrix.sync.aligned.m8n8.x4.shared.b16 {%0,%1,%2,%3}, [%4];"
                                 : "=r"(A[mi][0]), "=r"(A[mi][1]), "=r"(A[mi][2]), "=r"(A[mi][3])
                                 : "r"(ad));
                }
                #pragma unroll
                for (int g = 0; g < 4; ++g) {   // 2 token-tiles per x4
                    int row = g * 16 + (lane & 15);
                    int seg = kk * 2 + (lane >> 4);
                    uint32_t bd = smem_u32(xs + SWZ(row, seg));
                    uint32_t r0, r1, r2, r3;
                    asm volatile("ldmatrix.sync.aligned.m8n8.x4.shared.b16 {%0,%1,%2,%3}, [%4];"
                                 : "=r"(r0), "=r"(r1), "=r"(r2), "=r"(r3) : "r"(bd));
                    B[2 * g][0] = r0;     B[2 * g][1] = r2;
                    B[2 * g + 1][0] = r1; B[2 * g + 1][1] = r3;
                }
                #pragma unroll
                for (int mi = 0; mi < 2; ++mi)
                    #pragma unroll
                    for (int nt = 0; nt < 8; ++nt)
                        asm volatile("mma.sync.aligned.m16n8k16.row.col.f32.f16.f16.f32 "
                                     "{%0,%1,%2,%3}, {%4,%5,%6,%7}, {%8,%9}, {%0,%1,%2,%3};"
                                     : "+f"(acc[mi][nt][0]), "+f"(acc[mi][nt][1]),
                                       "+f"(acc[mi][nt][2]), "+f"(acc[mi][nt][3])
                                     : "r"(A[mi][0]), "r"(A[mi][1]), "r"(A[mi][2]), "r"(A[mi][3]),
                                       "r"(B[nt][0]), "r"(B[nt][1]));
            }
            bar_arrive(BAR_CONSUMED(b));
        }
    } else {
        // ================= PRODUCER =================
        const int pt = t - 128;                  // 0..127 = W row within tile
        const uint4* cb1 = (const uint4*)(smem + OFF_CB1 + (lane & 1) * 4096);
        const uint4* cb2 = (const uint4*)(smem + OFF_CB2 + (lane & 1) * 4096);
        const int* q1base = Qidxs  + (size_t)(m0 + pt) * (NF / 8) + split * (KSPLIT / 8);
        const int* q2base = Qidxs2 + (size_t)(m0 + pt) * (NF / 8) + split * (KSPLIT / 8);

        int4 c1[4], c2[4], n1[4], n2[4];
        #pragma unroll
        for (int i = 0; i < 4; ++i) {            // prime chunk 0 indices
            c1[i] = *(const int4*)(q1base + i * 4);
            c2[i] = *(const int4*)(q2base + i * 4);
        }

        for (int c = 0; c < CHUNKS; ++c) {
            const int b = c & 1;
            if (c >= 2) bar_sync(BAR_CONSUMED(b));

            // stage X tile via cp.async into swizzled layout
            const int k0 = split * KSPLIT + c * KTILE;
            const uint32_t xb = sb + (b ? OFF_X1 : OFF_X0);
            #pragma unroll
            for (int i = 0; i < 8; ++i) {
                int idx = pt + 128 * i, tok = idx >> 4, seg = idx & 15;
                cp_async16(xb + SWZ(tok, seg),
                           g_xh + (size_t)tok * NF + k0 + seg * 8);
            }
            asm volatile("cp.async.commit_group;" ::: "memory");

            // prefetch next chunk's indices (hidden under decode below)
            if (c + 1 < CHUNKS) {
                #pragma unroll
                for (int i = 0; i < 4; ++i) {
                    n1[i] = *(const int4*)(q1base + (c + 1) * 16 + i * 4);
                    n2[i] = *(const int4*)(q2base + (c + 1) * 16 + i * 4);
                }
            }

            // decode this chunk's 16 groups for row pt into swizzled W
            {
                int q1[16] = {c1[0].x, c1[0].y, c1[0].z, c1[0].w,
                              c1[1].x, c1[1].y, c1[1].z, c1[1].w,
                              c1[2].x, c1[2].y, c1[2].z, c1[2].w,
                              c1[3].x, c1[3].y, c1[3].z, c1[3].w};
                int q2[16] = {c2[0].x, c2[0].y, c2[0].z, c2[0].w,
                              c2[1].x, c2[1].y, c2[1].z, c2[1].w,
                              c2[2].x, c2[2].y, c2[2].z, c2[2].w,
                              c2[3].x, c2[3].y, c2[3].z, c2[3].w};
                char* wb = smem + (b ? OFF_W1 : OFF_W0);
                const uint32_t rbase = pt << 8;
                const uint32_t rx = (pt & 7) << 4;
                #pragma unroll
                for (int j = 0; j < 16; ++j) {
                    uint4 v1 = cb1[q1[j]], v2 = cb2[q2[j]];
                    __half2* h1 = (__half2*)&v1;
                    const __half2* h2 = (const __half2*)&v2;
                    h1[0] = __hadd2(h1[0], h2[0]); h1[1] = __hadd2(h1[1], h2[1]);
                    h1[2] = __hadd2(h1[2], h2[2]); h1[3] = __hadd2(h1[3], h2[3]);
                    *(uint4*)(wb + (rbase + (((uint32_t)(j << 4)) ^ rx))) = v1;
                }
            }

            asm volatile("cp.async.wait_group 0;" ::: "memory");
            bar_arrive(BAR_READY(b));

            #pragma unroll
            for (int i = 0; i < 4; ++i) { c1[i] = n1[i]; c2[i] = n2[i]; }
        }
    }

    // ---- epilogue: consumer regs -> smem transpose [tok][m] -> fp16 partials ----
    float* ob = (float*)(smem + OFF_W0);    // 64 * OBPAD * 4 = 33792 B (W bufs dead)
    __syncthreads();
    if (w < 4) {
        #pragma unroll
        for (int mi = 0; mi < 2; ++mi)
            #pragma unroll
            for (int nt = 0; nt < 8; ++nt) {
                int m = w * 32 + mi * 16 + (lane >> 2);
                int n = nt * 8 + (lane & 3) * 2;
                ob[n * OBPAD + m]           = acc[mi][nt][0];
                ob[(n + 1) * OBPAD + m]     = acc[mi][nt][1];
                ob[n * OBPAD + m + 8]       = acc[mi][nt][2];
                ob[(n + 1) * OBPAD + m + 8] = acc[mi][nt][3];
            }
    }
    __syncthreads();
    __half* dst = g_yph + (size_t)split * TOK * MF;
    #pragma unroll
    for (int i = 0; i < 4; ++i) {
        int idx = t + 256 * i;              // 0..1023: tok = idx>>4, 8-val seg
        int tok = idx >> 4, seg = idx & 15;
        const float* src = ob + tok * OBPAD + seg * 8;
        union { uint4 u; __half2 h[4]; } pk;
        #pragma unroll
        for (int e = 0; e < 4; ++e)
            pk.h[e] = __floats2half2_rn(src[2 * e], src[2 * e + 1]);
        *(uint4*)(dst + (size_t)tok * MF + m0 + seg * 8) = pk.u;
    }
}

// ---------------------------------------------------------------------------
// Kernel 3: fused split-reduce + H4-across-blocks + FHT-2048 + scale/SU -> out
//   grid = (TOK, 4), 512 threads; all 16 global loads batched first (MLP).
// ---------------------------------------------------------------------------
__global__ void __launch_bounds__(512) k_fht_out(float* __restrict__ out,
                                                 const float* __restrict__ SU,
                                                 const float* __restrict__ wsc_p) {
    __shared__ float s[2048 + 64];
    const int row = blockIdx.x, q = blockIdx.y, t = threadIdx.x, lane = t & 31;
    union { uint2 u2; __half2 h[2]; } pk[4][SPLITS];
    #pragma unroll
    for (int j = 0; j < 4; ++j)
        #pragma unroll
        for (int sp = 0; sp < SPLITS; ++sp)
            pk[j][sp].u2 = *(const uint2*)(g_yph + ((size_t)sp * TOK + row) * MF
                                           + j * 2048 + t * 4);
    float v[4], u[4];
    #pragma unroll
    for (int e = 0; e < 4; ++e) v[e] = 0.f;
    #pragma unroll
    for (int j = 0; j < 4; ++j) {
        const float sgn = (__popc(q & j) & 1) ? -1.f : 1.f;
        #pragma unroll
        for (int sp = 0; sp < SPLITS; ++sp) {
            float2 f0 = __half22float2(pk[j][sp].h[0]);
            float2 f1 = __half22float2(pk[j][sp].h[1]);
            v[0] += sgn * f0.x; v[1] += sgn * f0.y;
            v[2] += sgn * f1.x; v[3] += sgn * f1.y;
        }
    }
    fht2048_512(s, v, u, t, lane);
    const float sc = wsc_p[0] * 0.011048543456039806f;  // Wscale / sqrt(8192)
    const int l = t & 127, g = t >> 7;
    const int col = q * 2048 + l + 128 * g;
    float* op = out + (size_t)row * MF + col;
    const float* sup = SU + col;
    #pragma unroll
    for (int j = 0; j < 4; ++j)
        op[512 * j] = u[j] * sc * sup[512 * j];
}

// ---------------------------------------------------------------------------
extern "C" void kernel_launch(void* const* d_in, const int* in_sizes, int n_in,
                              void* d_out, int out_size) {
    const float* x      = (const float*)d_in[0];
    const int*   Qidxs  = (const int*)  d_in[1];
    const int*   Qidxs2 = (const int*)  d_in[2];
    const float* cb1    = (const float*)d_in[3];
    const float* cb2    = (const float*)d_in[4];
    const float* SU     = (const float*)d_in[5];
    const float* SV     = (const float*)d_in[6];
    const float* Wsc    = (const float*)d_in[7];
    const float* irs    = (const float*)d_in[8];
    float* out = (float*)d_out;

    cudaFuncSetAttribute(k_gemm, cudaFuncAttributeMaxDynamicSharedMemorySize, SMEM_SZ);

    k_fht_in<<<dim3(TOK, 4), 512>>>(x, SV);
    k_gemm<<<dim3(MF / MTILE, SPLITS), 256, SMEM_SZ>>>(Qidxs, Qidxs2, cb1, cb2, irs);
    k_fht_out<<<dim3(TOK, 4), 512>>>(out, SU, Wsc);
}